// round 2
// baseline (speedup 1.0000x reference)
#include <cuda_runtime.h>
#include <cuda_bf16.h>
#include <cstdio>

// Problem constants
#define BB   4
#define CC   256
#define HH   128
#define WW   128
#define KK   1000
#define POOLED 7
#define NBIN (POOLED*POOLED)          // 49
#define PER_ROI (CC*NBIN)             // 12544 floats per ROI

// 64 MB NHWC scratch (device global: the sanctioned no-alloc workaround)
__device__ float g_tfeat[BB * HH * WW * CC];

// ---------------------------------------------------------------------------
// Kernel 1: NCHW -> NHWC transpose. For each (b, y) row we transpose the
// C x W (256 x 128) matrix into W x C using 32x32 smem tiles.
// grid: (W/32, C/32, B*H), block: (32, 8)
// ---------------------------------------------------------------------------
__global__ void nchw_to_nhwc(const float* __restrict__ f) {
    __shared__ float tile[32][33];
    const int x0 = blockIdx.x * 32;
    const int c0 = blockIdx.y * 32;
    const int bz = blockIdx.z;
    const int b  = bz >> 7;       // /128
    const int y  = bz & 127;      // %128

    const int tx = threadIdx.x;
    const int ty = threadIdx.y;

    const float* src = f + (((size_t)(b * CC + c0) * HH + y) * WW + x0);
#pragma unroll
    for (int j = 0; j < 32; j += 8) {
        // read coalesced along x; channel stride is H*W
        tile[ty + j][tx] = src[(size_t)(ty + j) * (HH * WW) + tx];
    }
    __syncthreads();

    float* dst = g_tfeat + (((size_t)(b * HH + y) * WW + x0) * CC + c0);
#pragma unroll
    for (int j = 0; j < 32; j += 8) {
        // write coalesced along c
        dst[(size_t)(ty + j) * CC + tx] = tile[tx][ty + j];
    }
}

// ---------------------------------------------------------------------------
// Kernel 2: ROI Align. One CTA per ROI, 256 threads = channels.
// Sample coordinate tables (7 bins x up to 2 grid points, each axis)
// precomputed into smem. Bilinear taps read contiguous 1KB channel vectors
// from the NHWC scratch. Output staged in dynamic smem (c*49+bin layout,
// stride 49 -> bank-conflict-free) then written fully coalesced.
// ---------------------------------------------------------------------------
__global__ void roi_align_kernel(const float* __restrict__ boxes,
                                 float* __restrict__ out) {
    extern __shared__ float so[];            // PER_ROI floats = 50176 B
    __shared__ int   sxl[14], sxh[14], syl[14], syh[14];
    __shared__ float slx[14], shx[14], sly[14], shy[14];

    const int k   = blockIdx.x;
    const int tid = threadIdx.x;

    const float bf = boxes[k * 5 + 0];
    const float x1 = boxes[k * 5 + 1] * 0.25f;
    const float y1 = boxes[k * 5 + 2] * 0.25f;
    const float x2 = boxes[k * 5 + 3] * 0.25f;
    const float y2 = boxes[k * 5 + 4] * 0.25f;
    const int b = (int)bf;

    const float roi_w = fmaxf(x2 - x1, 1.0f);
    const float roi_h = fmaxf(y2 - y1, 1.0f);
    const float bin_w = roi_w * (1.0f / POOLED);
    const float bin_h = roi_h * (1.0f / POOLED);
    const int gw = (int)ceilf(roi_w * (1.0f / POOLED));
    const int gh = (int)ceilf(roi_h * (1.0f / POOLED));
    const int gw2 = min(gw, 2);
    const int gh2 = min(gh, 2);

    // Precompute per-axis sample tables: entries s = p*2 + i  (p=bin, i=grid idx)
    if (tid < 28) {
        const bool isy = tid >= 14;
        const int  s   = isy ? tid - 14 : tid;
        const int  p   = s >> 1;
        const int  i   = s & 1;
        const float start = isy ? y1 : x1;
        const float bs    = isy ? bin_h : bin_w;
        const int   g     = isy ? gh : gw;
        const float coord = start + (float)p * bs + ((float)i + 0.5f) * bs / (float)g;

        const bool valid = (coord >= -1.0f) && (coord <= 128.0f);
        float cc = fmaxf(coord, 0.0f);
        int lo = min((int)cc, 127);
        int hi = min(lo + 1, 127);
        float l = (lo >= 127) ? 0.0f : (cc - (float)lo);
        float h = 1.0f - l;
        if (!valid) { l = 0.0f; h = 0.0f; }   // zero both factors -> sample = 0
        if (isy) { syl[s] = lo; syh[s] = hi; sly[s] = l; shy[s] = h; }
        else     { sxl[s] = lo; sxh[s] = hi; slx[s] = l; shx[s] = h; }
    }
    __syncthreads();

    const float invn = 1.0f / (float)(gh * gw);
    const float* base = g_tfeat + (size_t)b * (HH * WW * CC) + tid;

#pragma unroll
    for (int py = 0; py < POOLED; ++py) {
#pragma unroll
        for (int px = 0; px < POOLED; ++px) {
            float acc = 0.0f;
            for (int iy = 0; iy < gh2; ++iy) {
                const int   ys = py * 2 + iy;
                const int   yl = syl[ys], yh = syh[ys];
                const float ly = sly[ys], hy = shy[ys];
                const float* rl = base + (size_t)yl * (WW * CC);
                const float* rh = base + (size_t)yh * (WW * CC);
                for (int jx = 0; jx < gw2; ++jx) {
                    const int   xs = px * 2 + jx;
                    const int   xl = sxl[xs], xh = sxh[xs];
                    const float lx = slx[xs], hx = shx[xs];
                    const float v00 = __ldg(rl + (size_t)xl * CC);
                    const float v01 = __ldg(rl + (size_t)xh * CC);
                    const float v10 = __ldg(rh + (size_t)xl * CC);
                    const float v11 = __ldg(rh + (size_t)xh * CC);
                    acc += hy * (hx * v00 + lx * v01) + ly * (hx * v10 + lx * v11);
                }
            }
            so[tid * NBIN + py * POOLED + px] = acc * invn;
        }
    }
    __syncthreads();

    // Coalesced write-out of the whole ROI block
    float* o = out + (size_t)k * PER_ROI;
    for (int i = tid; i < PER_ROI; i += 256) {
        o[i] = so[i];
    }
}

extern "C" void kernel_launch(void* const* d_in, const int* in_sizes, int n_in,
                              void* d_out, int out_size) {
    const float* features = (const float*)d_in[0];   // [4,256,128,128]
    const float* boxes    = (const float*)d_in[1];   // [1000,5]
    float* out = (float*)d_out;                      // [1000,256,7,7]

    (void)in_sizes; (void)n_in; (void)out_size;

    // Allow >48KB dynamic smem for the staging buffer (idempotent, no sync)
    static bool attr_set = false;
    if (!attr_set) {
        cudaFuncSetAttribute(roi_align_kernel,
                             cudaFuncAttributeMaxDynamicSharedMemorySize,
                             PER_ROI * (int)sizeof(float));
        attr_set = true;
    }

    // 1) Transpose NCHW -> NHWC scratch
    dim3 gT(WW / 32, CC / 32, BB * HH);
    dim3 bT(32, 8);
    nchw_to_nhwc<<<gT, bT>>>(features);

    // 2) ROI align from NHWC scratch
    roi_align_kernel<<<KK, 256, PER_ROI * (int)sizeof(float)>>>(boxes, out);
}

// round 3
// speedup vs baseline: 1.6041x; 1.6041x over previous
#include <cuda_runtime.h>
#include <cuda_bf16.h>

// Problem constants
#define BB   4
#define CC   256
#define HH   128
#define WW   128
#define KK   1000
#define POOLED 7
#define NBIN (POOLED*POOLED)          // 49
#define PER_ROI (CC*NBIN)             // 12544 floats per ROI
#define HWSZ (HH*WW)

// 64 MB NHWC scratch (device global: the sanctioned no-alloc workaround)
__device__ float g_tfeat[BB * HH * WW * CC];

// ---------------------------------------------------------------------------
// Kernel 1: NCHW -> NHWC transpose, float4 on both global sides.
// grid: (W/32, C/32, B*H), block: 256 flat.
// Phase 1: thread i reads float4 of 4 x-positions for channel row (i/8);
// Phase 2: thread i gathers 4 channels for x-column (i/8), writes float4.
// Both smem phases are provably bank-conflict-free (33-word row stride).
// ---------------------------------------------------------------------------
__global__ void nchw_to_nhwc(const float* __restrict__ f) {
    __shared__ float tile[32][33];
    const int i  = threadIdx.x;
    const int x0 = blockIdx.x * 32;
    const int c0 = blockIdx.y * 32;
    const int bz = blockIdx.z;
    const int b  = bz >> 7;
    const int y  = bz & 127;

    // Phase 1: read (c-row, 4 x) coalesced
    {
        const int cl = i >> 3;
        const int xq = i & 7;
        const float4 v = *(const float4*)(f +
            (((size_t)(b * CC + c0 + cl) * HH + y) * WW + x0 + 4 * xq));
        tile[cl][4 * xq + 0] = v.x;
        tile[cl][4 * xq + 1] = v.y;
        tile[cl][4 * xq + 2] = v.z;
        tile[cl][4 * xq + 3] = v.w;
    }
    __syncthreads();

    // Phase 2: gather 4 channels for one x, write float4 coalesced
    {
        const int xl = i >> 3;
        const int cq = i & 7;
        float4 w;
        w.x = tile[4 * cq + 0][xl];
        w.y = tile[4 * cq + 1][xl];
        w.z = tile[4 * cq + 2][xl];
        w.w = tile[4 * cq + 3][xl];
        *(float4*)(g_tfeat +
            (((size_t)(b * HH + y) * WW + x0 + xl) * CC + c0 + 4 * cq)) = w;
    }
}

// ---------------------------------------------------------------------------
// Kernel 2: ROI Align. One CTA per ROI, 256 threads = channels.
// gh2/gw2 are CTA-uniform -> dispatch to 4 fully-unrolled template bodies.
// Unrolling the px row gives 7 independent acc chains (up to 112 loads of
// MLP for the 2x2 case) to hide L2 latency.
// ---------------------------------------------------------------------------
template<int GH, int GW>
__device__ __forceinline__ void roi_body(
    int tid, const float* __restrict__ base,
    const int* __restrict__ sxl, const int* __restrict__ sxh,
    const float* __restrict__ slx, const float* __restrict__ shx,
    const int* __restrict__ syl, const int* __restrict__ syh,
    const float* __restrict__ sly, const float* __restrict__ shy,
    float* __restrict__ so)
{
    const float invn = 1.0f / (float)(GH * GW);
#pragma unroll
    for (int py = 0; py < POOLED; ++py) {
        const float* rlo[GH];
        const float* rhi[GH];
        float why[GH], wly[GH];
#pragma unroll
        for (int iy = 0; iy < GH; ++iy) {
            const int ys = py * 2 + iy;
            rlo[iy] = base + syl[ys] * (WW * CC);
            rhi[iy] = base + syh[ys] * (WW * CC);
            why[iy] = shy[ys];
            wly[iy] = sly[ys];
        }
#pragma unroll
        for (int px = 0; px < POOLED; ++px) {
            float acc = 0.0f;
#pragma unroll
            for (int jx = 0; jx < GW; ++jx) {
                const int xs = px * 2 + jx;
                const int xl = sxl[xs] * CC;
                const int xh = sxh[xs] * CC;
                const float lx = slx[xs];
                const float hx = shx[xs];
#pragma unroll
                for (int iy = 0; iy < GH; ++iy) {
                    const float v00 = __ldg(rlo[iy] + xl);
                    const float v01 = __ldg(rlo[iy] + xh);
                    const float v10 = __ldg(rhi[iy] + xl);
                    const float v11 = __ldg(rhi[iy] + xh);
                    acc += why[iy] * (hx * v00 + lx * v01)
                         + wly[iy] * (hx * v10 + lx * v11);
                }
            }
            so[tid * NBIN + py * POOLED + px] = acc * invn;
        }
    }
}

__global__ void __launch_bounds__(256, 4)
roi_align_kernel(const float* __restrict__ boxes, float* __restrict__ out) {
    extern __shared__ float so[];            // PER_ROI floats = 50176 B
    __shared__ int   sxl[14], sxh[14], syl[14], syh[14];
    __shared__ float slx[14], shx[14], sly[14], shy[14];

    const int k   = blockIdx.x;
    const int tid = threadIdx.x;

    const float bf = boxes[k * 5 + 0];
    const float x1 = boxes[k * 5 + 1] * 0.25f;
    const float y1 = boxes[k * 5 + 2] * 0.25f;
    const float x2 = boxes[k * 5 + 3] * 0.25f;
    const float y2 = boxes[k * 5 + 4] * 0.25f;
    const int b = (int)bf;

    const float roi_w = fmaxf(x2 - x1, 1.0f);
    const float roi_h = fmaxf(y2 - y1, 1.0f);
    const float bin_w = roi_w * (1.0f / POOLED);
    const float bin_h = roi_h * (1.0f / POOLED);
    const int gw = (int)ceilf(roi_w * (1.0f / POOLED));
    const int gh = (int)ceilf(roi_h * (1.0f / POOLED));
    const int gw2 = min(gw, 2);   // box sizes guarantee <= 2; min() for safety
    const int gh2 = min(gh, 2);

    // Precompute per-axis sample tables: entries s = p*2 + i  (p=bin, i=grid idx)
    if (tid < 28) {
        const bool isy = tid >= 14;
        const int  s   = isy ? tid - 14 : tid;
        const int  p   = s >> 1;
        const int  i   = s & 1;
        const float start = isy ? y1 : x1;
        const float bs    = isy ? bin_h : bin_w;
        const int   g     = isy ? gh : gw;
        const float coord = start + (float)p * bs + ((float)i + 0.5f) * bs / (float)g;

        const bool valid = (coord >= -1.0f) && (coord <= 128.0f);
        float cc = fmaxf(coord, 0.0f);
        int lo = min((int)cc, 127);
        int hi = min(lo + 1, 127);
        float l = (lo >= 127) ? 0.0f : (cc - (float)lo);
        float h = 1.0f - l;
        if (!valid) { l = 0.0f; h = 0.0f; }   // zero both factors -> sample = 0
        if (isy) { syl[s] = lo; syh[s] = hi; sly[s] = l; shy[s] = h; }
        else     { sxl[s] = lo; sxh[s] = hi; slx[s] = l; shx[s] = h; }
    }
    __syncthreads();

    const float* base = g_tfeat + (size_t)b * (HWSZ * CC) + tid;

    // CTA-uniform dispatch to fully-unrolled specializations
    if (gh2 == 1) {
        if (gw2 == 1) roi_body<1,1>(tid, base, sxl, sxh, slx, shx, syl, syh, sly, shy, so);
        else          roi_body<1,2>(tid, base, sxl, sxh, slx, shx, syl, syh, sly, shy, so);
    } else {
        if (gw2 == 1) roi_body<2,1>(tid, base, sxl, sxh, slx, shx, syl, syh, sly, shy, so);
        else          roi_body<2,2>(tid, base, sxl, sxh, slx, shx, syl, syh, sly, shy, so);
    }
    __syncthreads();

    // Vectorized coalesced write-out of the whole ROI block
    float4* o4 = (float4*)(out + (size_t)k * PER_ROI);
    const float4* s4 = (const float4*)so;
#pragma unroll 4
    for (int i = tid; i < PER_ROI / 4; i += 256) {
        o4[i] = s4[i];
    }
}

extern "C" void kernel_launch(void* const* d_in, const int* in_sizes, int n_in,
                              void* d_out, int out_size) {
    const float* features = (const float*)d_in[0];   // [4,256,128,128]
    const float* boxes    = (const float*)d_in[1];   // [1000,5]
    float* out = (float*)d_out;                      // [1000,256,7,7]

    (void)in_sizes; (void)n_in; (void)out_size;

    cudaFuncSetAttribute(roi_align_kernel,
                         cudaFuncAttributeMaxDynamicSharedMemorySize,
                         PER_ROI * (int)sizeof(float));

    // 1) Transpose NCHW -> NHWC scratch
    dim3 gT(WW / 32, CC / 32, BB * HH);
    nchw_to_nhwc<<<gT, 256>>>(features);

    // 2) ROI align from NHWC scratch
    roi_align_kernel<<<KK, 256, PER_ROI * (int)sizeof(float)>>>(boxes, out);
}